// round 12
// baseline (speedup 1.0000x reference)
#include <cuda_runtime.h>
#include <cuda_bf16.h>
#include <math.h>
#include <stdint.h>

// Problem constants
#define BB 4
#define NN 16384
#define MM 512
#define COLS1 131072   // BB*MM*64  (ball branch columns)
#define COLS2 18432    // BB*MM*9   (knn branch columns)
#define COLSN 2048     // BB*MM

// ---------------- static scratch (no allocations allowed) ----------------
__device__ __nv_bfloat16 d_bufA[128 * 131072];   // 32 MiB ping (bf16)
__device__ __nv_bfloat16 d_bufB[128 * 131072];   // 32 MiB pong (bf16)
__device__ __nv_bfloat16 d_X0[6 * 131072];       // gathered ball input (6 x COLS1)
__device__ __nv_bfloat16 d_H[640 * 2048];        // rows 0..127 feat1, 128..639 feat2
__device__ __nv_bfloat16 d_tmp1[512 * 2048];     // per-node maxes (bf16)
__device__ float         d_tmp2[512 * 2048];     // Z (per-node half + bias), fp32
__device__ int   d_ballidx[131072];              // (B*M, 64)
__device__ int   d_knnidx[18432];                // (B*M, 9)

// ---------------- bf16 helpers -------------------------------------------
__device__ __forceinline__ uint32_t pack_bf16(float lo, float hi) {
    __nv_bfloat162 h = __floats2bfloat162_rn(lo, hi);  // .x = lo (low 16 bits)
    return *reinterpret_cast<uint32_t*>(&h);
}

__device__ __forceinline__ void mma_bf16(float c[4], const uint32_t a[4], const uint32_t b[2]) {
    asm volatile(
        "mma.sync.aligned.m16n8k16.row.col.f32.bf16.bf16.f32 "
        "{%0,%1,%2,%3}, {%4,%5,%6,%7}, {%8,%9}, {%0,%1,%2,%3};"
        : "+f"(c[0]), "+f"(c[1]), "+f"(c[2]), "+f"(c[3])
        : "r"(a[0]), "r"(a[1]), "r"(a[2]), "r"(a[3]), "r"(b[0]), "r"(b[1]));
}

// ---------------- bf16 tensor-core GEMM, 2-stage pipelined ---------------
// C[.. x Ncols] = act(W[.. x lda (use K cols)] @ X[K x Ncols] + bias)
// W fp32, X bf16 row-major, C bf16 (store_bf16=1) or fp32 (0).
// bias_mode: 0 = bias[row]; 1 = bias[row*COLSN + (col>>6)]; 2 = bias[row*COLSN + col/9]
// Block tile: BM = WR*32 rows x BN = WC*64 cols, BK = 32 (16 packed bf16x2 rows).
template<int WR, int WC>
__global__ void __launch_bounds__(WR*WC*32, 2)
gemm_bf16(const float* __restrict__ W, int lda,
          const __nv_bfloat16* __restrict__ X,
          const float* __restrict__ bias, int bias_mode,
          void* __restrict__ Cout, int store_bf16,
          int K, int Ncols, int do_relu)
{
    constexpr int BM = WR * 32;
    constexpr int BN = WC * 64;
    constexpr int NT = WR * WC * 32;
    constexpr int KP = 16;              // packed k-pair rows per tile
    constexpr int SA = BM + 8;
    constexpr int SB = BN + 8;
    constexpr int AS = NT / BM;         // A loader k-stride
    constexpr int AI = KP / AS;         // A loader iterations
    constexpr int N8 = BN / 8;          // B loader: 8 bf16 per uint4
    constexpr int BS = NT / N8;         // B loader k-stride
    constexpr int BI = KP / BS;         // B loader iterations

    __shared__ __align__(16) uint32_t As[2][KP][SA];
    __shared__ __align__(16) uint32_t Bs[2][KP][SB];

    const int tid  = threadIdx.x;
    const int lane = tid & 31;
    const int wid  = tid >> 5;
    const int g = lane >> 2;
    const int t = lane & 3;
    const int wm0 = (wid / WC) * 32;
    const int wn0 = (wid % WC) * 64;
    const int co0  = blockIdx.y * BM;
    const int col0 = blockIdx.x * BN;

    const int a_row = tid % BM;
    const int a_k0  = tid / BM;
    const int b_n8  = tid % N8;
    const int b_k0  = tid / N8;

    float acc[2][8][4];
#pragma unroll
    for (int mi = 0; mi < 2; mi++)
#pragma unroll
        for (int nj = 0; nj < 8; nj++)
#pragma unroll
            for (int q = 0; q < 4; q++) acc[mi][nj][q] = 0.f;

    uint32_t aReg[AI];
    uint4    bReg[BI][2];
    const float* wp = W + (size_t)(co0 + a_row) * lda;

    auto load_tiles = [&](int k0) {
#pragma unroll
        for (int i = 0; i < AI; i++) {
            int kg = k0 + 2 * (a_k0 + i * AS);
            float v0 = (kg     < K) ? __ldg(wp + kg)     : 0.f;
            float v1 = (kg + 1 < K) ? __ldg(wp + kg + 1) : 0.f;
            aReg[i] = pack_bf16(v0, v1);
        }
#pragma unroll
        for (int i = 0; i < BI; i++) {
            int kg = k0 + 2 * (b_k0 + i * BS);
            uint4 u0 = make_uint4(0, 0, 0, 0), u1 = u0;
            if (kg < K)
                u0 = *reinterpret_cast<const uint4*>(&X[(size_t)kg * Ncols + col0 + b_n8 * 8]);
            if (kg + 1 < K)
                u1 = *reinterpret_cast<const uint4*>(&X[(size_t)(kg + 1) * Ncols + col0 + b_n8 * 8]);
            bReg[i][0] = make_uint4(__byte_perm(u0.x, u1.x, 0x5410), __byte_perm(u0.x, u1.x, 0x7632),
                                    __byte_perm(u0.y, u1.y, 0x5410), __byte_perm(u0.y, u1.y, 0x7632));
            bReg[i][1] = make_uint4(__byte_perm(u0.z, u1.z, 0x5410), __byte_perm(u0.z, u1.z, 0x7632),
                                    __byte_perm(u0.w, u1.w, 0x5410), __byte_perm(u0.w, u1.w, 0x7632));
        }
    };
    auto store_stage = [&](int s) {
#pragma unroll
        for (int i = 0; i < AI; i++)
            As[s][a_k0 + i * AS][a_row] = aReg[i];
#pragma unroll
        for (int i = 0; i < BI; i++) {
            *reinterpret_cast<uint4*>(&Bs[s][b_k0 + i * BS][b_n8 * 8])     = bReg[i][0];
            *reinterpret_cast<uint4*>(&Bs[s][b_k0 + i * BS][b_n8 * 8 + 4]) = bReg[i][1];
        }
    };

    const int nIters = (K + 31) / 32;
    load_tiles(0);
    store_stage(0);
    __syncthreads();

    for (int it = 0; ; it++) {
        const int cur = it & 1;
        const bool more = (it + 1 < nIters);
        if (more) load_tiles((it + 1) * 32);   // LDGs overlap compute below

#pragma unroll
        for (int ks = 0; ks < 2; ks++) {
            const int kr = ks * 8;
            uint32_t a[2][4], b[8][2];
#pragma unroll
            for (int mi = 0; mi < 2; mi++) {
                int m = wm0 + mi * 16;
                a[mi][0] = As[cur][kr + t][m + g];
                a[mi][1] = As[cur][kr + t][m + g + 8];
                a[mi][2] = As[cur][kr + t + 4][m + g];
                a[mi][3] = As[cur][kr + t + 4][m + g + 8];
            }
#pragma unroll
            for (int nj = 0; nj < 8; nj++) {
                int n = wn0 + nj * 8;
                b[nj][0] = Bs[cur][kr + t][n + g];
                b[nj][1] = Bs[cur][kr + t + 4][n + g];
            }
#pragma unroll
            for (int mi = 0; mi < 2; mi++)
#pragma unroll
                for (int nj = 0; nj < 8; nj++)
                    mma_bf16(acc[mi][nj], a[mi], b[nj]);
        }

        if (!more) break;
        store_stage(1 - cur);
        __syncthreads();
    }

    // epilogue: bias (3 modes) + relu, bf16x2 or fp32 stores
    __nv_bfloat16* Cb = (__nv_bfloat16*)Cout;
    float*         Cf = (float*)Cout;
#pragma unroll
    for (int mi = 0; mi < 2; mi++) {
        const int r0 = co0 + wm0 + mi * 16 + g;
        const int r1 = r0 + 8;
        float brs0 = 0.f, brs1 = 0.f;
        if (bias_mode == 0) { brs0 = bias[r0]; brs1 = bias[r1]; }
#pragma unroll
        for (int nj = 0; nj < 8; nj++) {
            const int cb = col0 + wn0 + nj * 8 + 2 * t;
            float b00, b01, b10, b11;
            if (bias_mode == 0) {
                b00 = b01 = brs0; b10 = b11 = brs1;
            } else if (bias_mode == 1) {
                int nid = cb >> 6;
                b00 = b01 = bias[(size_t)r0 * COLSN + nid];
                b10 = b11 = bias[(size_t)r1 * COLSN + nid];
            } else {
                int n0 = cb / 9, n1 = (cb + 1) / 9;
                b00 = bias[(size_t)r0 * COLSN + n0];
                b01 = bias[(size_t)r0 * COLSN + n1];
                b10 = bias[(size_t)r1 * COLSN + n0];
                b11 = bias[(size_t)r1 * COLSN + n1];
            }
            float v0 = acc[mi][nj][0] + b00;
            float v1 = acc[mi][nj][1] + b01;
            float v2 = acc[mi][nj][2] + b10;
            float v3 = acc[mi][nj][3] + b11;
            if (do_relu) {
                v0 = fmaxf(v0, 0.f); v1 = fmaxf(v1, 0.f);
                v2 = fmaxf(v2, 0.f); v3 = fmaxf(v3, 0.f);
            }
            if (store_bf16) {
                *reinterpret_cast<uint32_t*>(&Cb[(size_t)r0 * Ncols + cb]) = pack_bf16(v0, v1);
                *reinterpret_cast<uint32_t*>(&Cb[(size_t)r1 * Ncols + cb]) = pack_bf16(v2, v3);
            } else {
                *reinterpret_cast<float2*>(&Cf[(size_t)r0 * Ncols + cb]) = make_float2(v0, v1);
                *reinterpret_cast<float2*>(&Cf[(size_t)r1 * Ncols + cb]) = make_float2(v2, v3);
            }
        }
    }
}

// ---------------- ball query: first 64 in-ball indices in index order -----
__global__ void ball_query_kernel(const float* __restrict__ x,
                                  const float* __restrict__ node,
                                  int* __restrict__ idxout)
{
    int w = (blockIdx.x * blockDim.x + threadIdx.x) >> 5;
    int lane = threadIdx.x & 31;
    if (w >= BB * MM) return;
    int b = w / MM, m = w % MM;
    float nx = node[(b * 3 + 0) * MM + m];
    float ny = node[(b * 3 + 1) * MM + m];
    float nz = node[(b * 3 + 2) * MM + m];
    const float* xb = x + (size_t)b * 3 * NN;
    int base = w * 64;
    int total = 0;
    int firstJ = -1;
    for (int j0 = 0; j0 < NN; j0 += 32) {
        int j = j0 + lane;
        float dx = xb[j] - nx;
        float dy = xb[NN + j] - ny;
        float dz = xb[2 * NN + j] - nz;
        float d = dx * dx + dy * dy + dz * dz;
        bool hit = d < 4.0f;
        unsigned mask = __ballot_sync(0xffffffffu, hit);
        if (firstJ < 0 && mask) firstJ = j0 + __ffs(mask) - 1;
        int pos = total + __popc(mask & ((1u << lane) - 1u));
        if (hit && pos < 64) idxout[base + pos] = j;
        total += __popc(mask);
        if (total >= 64) break;
    }
    if (total < 64) {
        int f = (firstJ < 0) ? 0 : firstJ;
        for (int p = total + lane; p < 64; p += 32) idxout[base + p] = f;
    }
}

// ---------------- gather ball neighborhood: X0 (6 x COLS1), bf16 ----------
__global__ void gather_xb_kernel(const float* __restrict__ x,
                                 const float* __restrict__ sn,
                                 const float* __restrict__ node,
                                 const int* __restrict__ idx,
                                 __nv_bfloat16* __restrict__ X0)
{
    int col = blockIdx.x * blockDim.x + threadIdx.x;
    if (col >= COLS1) return;
    int nodeid = col >> 6;          // b*MM + m
    int b = nodeid / MM, m = nodeid % MM;
    int j = idx[col];
    const float* xb = x  + (size_t)b * 3 * NN;
    const float* sb = sn + (size_t)b * 3 * NN;
    X0[(size_t)0 * COLS1 + col] = __float2bfloat16(xb[j]          - node[(b * 3 + 0) * MM + m]);
    X0[(size_t)1 * COLS1 + col] = __float2bfloat16(xb[NN + j]     - node[(b * 3 + 1) * MM + m]);
    X0[(size_t)2 * COLS1 + col] = __float2bfloat16(xb[2 * NN + j] - node[(b * 3 + 2) * MM + m]);
    X0[(size_t)3 * COLS1 + col] = __float2bfloat16(sb[j]);
    X0[(size_t)4 * COLS1 + col] = __float2bfloat16(sb[NN + j]);
    X0[(size_t)5 * COLS1 + col] = __float2bfloat16(sb[2 * NN + j]);
}

// -------- per-node max over k=64 (bf16 in/out). grid(COLSN, rows/8), blk(32,8)
__global__ void max64_rows_kernel(const __nv_bfloat16* __restrict__ f,
                                  __nv_bfloat16* __restrict__ Hrows)
{
    int nodeid = blockIdx.x;
    int row = blockIdx.y * 8 + threadIdx.y;
    int lane = threadIdx.x;          // 0..31
    __nv_bfloat162 p = *reinterpret_cast<const __nv_bfloat162*>(
        &f[(size_t)row * COLS1 + nodeid * 64 + lane * 2]);
    float v = fmaxf(__bfloat162float(p.x), __bfloat162float(p.y));
#pragma unroll
    for (int o = 16; o; o >>= 1) v = fmaxf(v, __shfl_xor_sync(0xffffffffu, v, o));
    if (lane == 0) Hrows[(size_t)row * COLSN + nodeid] = __float2bfloat16(v);
}

// -------- per-node max over k=9 (bf16 in/out) -----------------------------
__global__ void max9_rows_kernel(const __nv_bfloat16* __restrict__ g,
                                 __nv_bfloat16* __restrict__ Hrows, int rows)
{
    int e = blockIdx.x * blockDim.x + threadIdx.x;
    if (e >= rows * COLSN) return;
    int row = e / COLSN, nid = e % COLSN;
    size_t base = (size_t)row * COLS2 + nid * 9;
    float mx = -3.4e38f;
#pragma unroll
    for (int k = 0; k < 9; k++) mx = fmaxf(mx, __bfloat162float(g[base + k]));
    Hrows[(size_t)row * COLSN + nid] = __float2bfloat16(mx);
}

// ---------------- 9-NN among nodes (tie-break: smaller index) -------------
__global__ void knn_select_kernel(const float* __restrict__ node,
                                  int* __restrict__ knnidx)
{
    int nid = blockIdx.x;           // 0..2047
    int b = nid >> 9, m = nid & 511;
    int j = threadIdx.x;            // 0..511
    __shared__ float rd[16];
    __shared__ int   ri[16];
    __shared__ int   sbest;
    float nx = node[(b * 3 + 0) * MM + m];
    float ny = node[(b * 3 + 1) * MM + m];
    float nz = node[(b * 3 + 2) * MM + m];
    float dx = node[(b * 3 + 0) * MM + j] - nx;
    float dy = node[(b * 3 + 1) * MM + j] - ny;
    float dz = node[(b * 3 + 2) * MM + j] - nz;
    float d = dx * dx + dy * dy + dz * dz;
    for (int t = 0; t < 9; t++) {
        float bd = d; int bi = j;
#pragma unroll
        for (int o = 16; o; o >>= 1) {
            float od = __shfl_xor_sync(0xffffffffu, bd, o);
            int   oi = __shfl_xor_sync(0xffffffffu, bi, o);
            if (od < bd || (od == bd && oi < bi)) { bd = od; bi = oi; }
        }
        if ((j & 31) == 0) { rd[j >> 5] = bd; ri[j >> 5] = bi; }
        __syncthreads();
        if (j == 0) {
            float best = rd[0]; int besti = ri[0];
            for (int w = 1; w < 16; w++)
                if (rd[w] < best || (rd[w] == best && ri[w] < besti)) { best = rd[w]; besti = ri[w]; }
            knnidx[nid * 9 + t] = besti;
            sbest = besti;
        }
        __syncthreads();
        if (j == sbest) d = 3.4e38f;
    }
}

// -------- gather knn inputs: g0 (131 x COLS2) bf16 ------------------------
__global__ void gather_knn_kernel(const float* __restrict__ node,
                                  const __nv_bfloat16* __restrict__ H,  // feat1
                                  const int* __restrict__ knnidx,
                                  __nv_bfloat16* __restrict__ g0)
{
    int e = blockIdx.x * blockDim.x + threadIdx.x;
    if (e >= 131 * COLS2) return;
    int row = e / COLS2, col = e % COLS2;
    int nid = col / 9;
    int b = nid >> 9, m = nid & 511;
    int j = knnidx[col];
    __nv_bfloat16 v;
    if (row < 3)
        v = __float2bfloat16(node[(b * 3 + row) * MM + j] - node[(b * 3 + row) * MM + m]);
    else
        v = H[(size_t)(row - 3) * COLSN + b * MM + j];
    g0[e] = v;
}

// -------- head: mlp3 (4x256) + softplus + assemble final output ----------
__global__ void head_kernel(const __nv_bfloat16* __restrict__ m2,  // 256 x 2048
                            const float* __restrict__ w3,          // 4 x 256
                            const float* __restrict__ b3,          // 4
                            const float* __restrict__ node,
                            float* __restrict__ out)
{
    int col = blockIdx.x * blockDim.x + threadIdx.x;
    if (col >= COLSN) return;
    int b = col >> 9, m = col & 511;
    float acc0 = b3[0], acc1 = b3[1], acc2 = b3[2], acc3 = b3[3];
    for (int ci = 0; ci < 256; ci++) {
        float xv = __bfloat162float(m2[(size_t)ci * COLSN + col]);
        acc0 += w3[0 * 256 + ci] * xv;
        acc1 += w3[1 * 256 + ci] * xv;
        acc2 += w3[2 * 256 + ci] * xv;
        acc3 += w3[3 * 256 + ci] * xv;
    }
    float kv[3] = {acc0, acc1, acc2};
#pragma unroll
    for (int c = 0; c < 3; c++) {
        float nv = node[(b * 3 + c) * MM + m];
        out[(b * 3 + c) * MM + m] = nv;                   // node passthrough
        out[6144 + (b * 3 + c) * MM + m] = kv[c] + nv;    // keypoints
    }
    float s = acc3;
    float sp = fmaxf(s, 0.f) + log1pf(expf(-fabsf(s)));
    out[12288 + b * MM + m] = sp + 0.001f;
}

// ------------------------------- launcher --------------------------------
extern "C" void kernel_launch(void* const* d_in, const int* in_sizes, int n_in,
                              void* d_out, int out_size)
{
    const float* x    = (const float*)d_in[0];
    const float* sn   = (const float*)d_in[1];
    const float* node = (const float*)d_in[2];
    const float* conv1_w = (const float*)d_in[3];  const float* conv1_b = (const float*)d_in[4];
    const float* conv2_w = (const float*)d_in[5];  const float* conv2_b = (const float*)d_in[6];
    const float* conv3_w = (const float*)d_in[7];  const float* conv3_b = (const float*)d_in[8];
    const float* conv4_w = (const float*)d_in[9];  const float* conv4_b = (const float*)d_in[10];
    const float* conv5_w = (const float*)d_in[11]; const float* conv5_b = (const float*)d_in[12];
    const float* knnb1_w = (const float*)d_in[13]; const float* knnb1_b = (const float*)d_in[14];
    const float* knnb2_w = (const float*)d_in[15]; const float* knnb2_b = (const float*)d_in[16];
    const float* knnb3_w = (const float*)d_in[17]; const float* knnb3_b = (const float*)d_in[18];
    const float* knna1_w = (const float*)d_in[19]; const float* knna1_b = (const float*)d_in[20];
    const float* knna2_w = (const float*)d_in[21]; const float* knna2_b = (const float*)d_in[22];
    const float* mlp1_w  = (const float*)d_in[23]; const float* mlp1_b  = (const float*)d_in[24];
    const float* mlp2_w  = (const float*)d_in[25]; const float* mlp2_b  = (const float*)d_in[26];
    const float* mlp3_w  = (const float*)d_in[27]; const float* mlp3_b  = (const float*)d_in[28];
    float* out = (float*)d_out;

    __nv_bfloat16 *bufA, *bufB, *X0, *H, *tmp1;
    float *tmp2;
    int *ballidx, *knnidx;
    cudaGetSymbolAddress((void**)&bufA, d_bufA);
    cudaGetSymbolAddress((void**)&bufB, d_bufB);
    cudaGetSymbolAddress((void**)&X0,   d_X0);
    cudaGetSymbolAddress((void**)&H,    d_H);
    cudaGetSymbolAddress((void**)&tmp1, d_tmp1);
    cudaGetSymbolAddress((void**)&tmp2, d_tmp2);
    cudaGetSymbolAddress((void**)&ballidx, d_ballidx);
    cudaGetSymbolAddress((void**)&knnidx,  d_knnidx);

    // ---- ball branch ----
    ball_query_kernel<<<(BB * MM * 32 + 255) / 256, 256>>>(x, node, ballidx);
    gather_xb_kernel<<<(COLS1 + 255) / 256, 256>>>(x, sn, node, ballidx, X0);

    // conv1..3: M=64 -> <2,4> (BM=64, BN=256)
    gemm_bf16<2, 4><<<dim3(COLS1 / 256, 1), 256>>>(conv1_w, 6,  X0,   conv1_b, 0, bufA, 1, 6,  COLS1, 1);
    gemm_bf16<2, 4><<<dim3(COLS1 / 256, 1), 256>>>(conv2_w, 64, bufA, conv2_b, 0, bufB, 1, 64, COLS1, 1);
    gemm_bf16<2, 4><<<dim3(COLS1 / 256, 1), 256>>>(conv3_w, 64, bufB, conv3_b, 0, bufA, 1, 64, COLS1, 1);

    // fmax (64 x 2048), then Z4 = conv4_w[:,64:128] @ fmax + b4 (fp32, no relu)
    max64_rows_kernel<<<dim3(COLSN, 8), dim3(32, 8)>>>(bufA, tmp1);
    gemm_bf16<4, 2><<<dim3(COLSN / 128, 1), 256>>>(conv4_w + 64, 128, tmp1, conv4_b, 0, tmp2, 0, 64, COLSN, 0);
    // conv4: relu(conv4_w[:,0:64] @ f3 + Z4[row][col>>6])
    gemm_bf16<4, 2><<<dim3(COLS1 / 128, 1), 256>>>(conv4_w, 128, bufA, tmp2, 1, bufB, 1, 64, COLS1, 1);
    gemm_bf16<4, 2><<<dim3(COLS1 / 128, 1), 256>>>(conv5_w, 128, bufB, conv5_b, 0, bufA, 1, 128, COLS1, 1);
    max64_rows_kernel<<<dim3(COLSN, 16), dim3(32, 8)>>>(bufA, H);   // feat1 -> H rows 0..127

    // ---- knn branch ----
    knn_select_kernel<<<COLSN, 512>>>(node, knnidx);
    gather_knn_kernel<<<(131 * COLS2 + 255) / 256, 256>>>(node, H, knnidx, bufA);
    gemm_bf16<4, 2><<<dim3(COLS2 / 128, 2), 256>>>(knnb1_w, 131, bufA, knnb1_b, 0, bufB, 1, 131, COLS2, 1);
    gemm_bf16<4, 2><<<dim3(COLS2 / 128, 2), 256>>>(knnb2_w, 256, bufB, knnb2_b, 0, bufA, 1, 256, COLS2, 1);
    gemm_bf16<4, 2><<<dim3(COLS2 / 128, 2), 256>>>(knnb3_w, 256, bufA, knnb3_b, 0, bufB, 1, 256, COLS2, 1);

    // gmax (256 x 2048), then Zk = knna1_w[:,256:512] @ gmax + b (fp32, no relu)
    max9_rows_kernel<<<(256 * COLSN + 255) / 256, 256>>>(bufB, tmp1, 256);
    gemm_bf16<4, 2><<<dim3(COLSN / 128, 4), 256>>>(knna1_w + 256, 512, tmp1, knna1_b, 0, tmp2, 0, 256, COLSN, 0);
    // knna1: relu(knna1_w[:,0:256] @ g3 + Zk[row][col/9])
    gemm_bf16<4, 2><<<dim3(COLS2 / 128, 4), 256>>>(knna1_w, 512, bufB, tmp2, 2, bufA, 1, 256, COLS2, 1);
    gemm_bf16<4, 2><<<dim3(COLS2 / 128, 4), 256>>>(knna2_w, 512, bufA, knna2_b, 0, bufB, 1, 512, COLS2, 1);
    max9_rows_kernel<<<(512 * COLSN + 255) / 256, 256>>>(bufB, H + (size_t)128 * COLSN, 512);

    // ---- mlp head ----
    gemm_bf16<4, 2><<<dim3(COLSN / 128, 4), 256>>>(mlp1_w, 640, H,    mlp1_b, 0, bufA, 1, 640, COLSN, 1);
    gemm_bf16<4, 2><<<dim3(COLSN / 128, 2), 256>>>(mlp2_w, 512, bufA, mlp2_b, 0, bufB, 1, 512, COLSN, 1);
    head_kernel<<<(COLSN + 255) / 256, 256>>>(bufB, mlp3_w, mlp3_b, node, out);

    (void)in_sizes; (void)n_in; (void)out_size;
}

// round 13
// speedup vs baseline: 1.0001x; 1.0001x over previous
#include <cuda_runtime.h>
#include <cuda_bf16.h>
#include <math.h>
#include <stdint.h>

// Problem constants
#define BB 4
#define NN 16384
#define MM 512
#define COLS1 131072   // BB*MM*64  (ball branch columns)
#define COLS2 18432    // BB*MM*9   (knn branch columns)
#define COLSN 2048     // BB*MM

// ---------------- static scratch (no allocations allowed) ----------------
__device__ __nv_bfloat16 d_bufA[128 * 131072];   // 32 MiB ping (bf16)
__device__ __nv_bfloat16 d_bufB[128 * 131072];   // 32 MiB pong (bf16)
__device__ __nv_bfloat16 d_X0[6 * 131072];       // gathered ball input (6 x COLS1)
__device__ __nv_bfloat16 d_H[640 * 2048];        // rows 0..127 feat1, 128..639 feat2
__device__ __nv_bfloat16 d_tmp1[512 * 2048];     // per-node maxes (bf16)
__device__ float         d_tmp2[512 * 2048];     // Z (per-node half + bias), fp32
__device__ int   d_ballidx[131072];              // (B*M, 64)
__device__ int   d_knnidx[18432];                // (B*M, 9)

// ---------------- bf16 helpers -------------------------------------------
__device__ __forceinline__ uint32_t pack_bf16(float lo, float hi) {
    __nv_bfloat162 h = __floats2bfloat162_rn(lo, hi);  // .x = lo (low 16 bits)
    return *reinterpret_cast<uint32_t*>(&h);
}

__device__ __forceinline__ void mma_bf16(float c[4], const uint32_t a[4], const uint32_t b[2]) {
    asm volatile(
        "mma.sync.aligned.m16n8k16.row.col.f32.bf16.bf16.f32 "
        "{%0,%1,%2,%3}, {%4,%5,%6,%7}, {%8,%9}, {%0,%1,%2,%3};"
        : "+f"(c[0]), "+f"(c[1]), "+f"(c[2]), "+f"(c[3])
        : "r"(a[0]), "r"(a[1]), "r"(a[2]), "r"(a[3]), "r"(b[0]), "r"(b[1]));
}

// ---------------- bf16 tensor-core GEMM, 2-stage pipelined ---------------
// C[.. x Ncols] = act(W[.. x lda (use K cols)] @ X[K x Ncols] + bias)
// W fp32, X bf16 row-major, C bf16 (store_bf16=1) or fp32 (0).
// bias_mode: 0 = bias[row]; 1 = bias[row*COLSN + (col>>6)]; 2 = bias[row*COLSN + col/9]
// Block tile: BM = WR*32 rows x BN = WC*64 cols, BK = 32 (16 packed bf16x2 rows).
template<int WR, int WC>
__global__ void __launch_bounds__(WR*WC*32, 2)
gemm_bf16(const float* __restrict__ W, int lda,
          const __nv_bfloat16* __restrict__ X,
          const float* __restrict__ bias, int bias_mode,
          void* __restrict__ Cout, int store_bf16,
          int K, int Ncols, int do_relu)
{
    constexpr int BM = WR * 32;
    constexpr int BN = WC * 64;
    constexpr int NT = WR * WC * 32;
    constexpr int KP = 16;              // packed k-pair rows per tile
    constexpr int SA = BM + 8;
    constexpr int SB = BN + 8;
    constexpr int AS = NT / BM;         // A loader k-stride
    constexpr int AI = KP / AS;         // A loader iterations
    constexpr int N8 = BN / 8;          // B loader: 8 bf16 per uint4
    constexpr int BS = NT / N8;         // B loader k-stride
    constexpr int BI = KP / BS;         // B loader iterations

    __shared__ __align__(16) uint32_t As[2][KP][SA];
    __shared__ __align__(16) uint32_t Bs[2][KP][SB];

    const int tid  = threadIdx.x;
    const int lane = tid & 31;
    const int wid  = tid >> 5;
    const int g = lane >> 2;
    const int t = lane & 3;
    const int wm0 = (wid / WC) * 32;
    const int wn0 = (wid % WC) * 64;
    const int co0  = blockIdx.y * BM;
    const int col0 = blockIdx.x * BN;

    const int a_row = tid % BM;
    const int a_k0  = tid / BM;
    const int b_n8  = tid % N8;
    const int b_k0  = tid / N8;

    float acc[2][8][4];
#pragma unroll
    for (int mi = 0; mi < 2; mi++)
#pragma unroll
        for (int nj = 0; nj < 8; nj++)
#pragma unroll
            for (int q = 0; q < 4; q++) acc[mi][nj][q] = 0.f;

    uint32_t aReg[AI];
    uint4    bReg[BI][2];
    const float* wp = W + (size_t)(co0 + a_row) * lda;

    auto load_tiles = [&](int k0) {
#pragma unroll
        for (int i = 0; i < AI; i++) {
            int kg = k0 + 2 * (a_k0 + i * AS);
            float v0 = (kg     < K) ? __ldg(wp + kg)     : 0.f;
            float v1 = (kg + 1 < K) ? __ldg(wp + kg + 1) : 0.f;
            aReg[i] = pack_bf16(v0, v1);
        }
#pragma unroll
        for (int i = 0; i < BI; i++) {
            int kg = k0 + 2 * (b_k0 + i * BS);
            uint4 u0 = make_uint4(0, 0, 0, 0), u1 = u0;
            if (kg < K)
                u0 = *reinterpret_cast<const uint4*>(&X[(size_t)kg * Ncols + col0 + b_n8 * 8]);
            if (kg + 1 < K)
                u1 = *reinterpret_cast<const uint4*>(&X[(size_t)(kg + 1) * Ncols + col0 + b_n8 * 8]);
            bReg[i][0] = make_uint4(__byte_perm(u0.x, u1.x, 0x5410), __byte_perm(u0.x, u1.x, 0x7632),
                                    __byte_perm(u0.y, u1.y, 0x5410), __byte_perm(u0.y, u1.y, 0x7632));
            bReg[i][1] = make_uint4(__byte_perm(u0.z, u1.z, 0x5410), __byte_perm(u0.z, u1.z, 0x7632),
                                    __byte_perm(u0.w, u1.w, 0x5410), __byte_perm(u0.w, u1.w, 0x7632));
        }
    };
    auto store_stage = [&](int s) {
#pragma unroll
        for (int i = 0; i < AI; i++)
            As[s][a_k0 + i * AS][a_row] = aReg[i];
#pragma unroll
        for (int i = 0; i < BI; i++) {
            *reinterpret_cast<uint4*>(&Bs[s][b_k0 + i * BS][b_n8 * 8])     = bReg[i][0];
            *reinterpret_cast<uint4*>(&Bs[s][b_k0 + i * BS][b_n8 * 8 + 4]) = bReg[i][1];
        }
    };

    const int nIters = (K + 31) / 32;
    load_tiles(0);
    store_stage(0);
    __syncthreads();

    for (int it = 0; ; it++) {
        const int cur = it & 1;
        const bool more = (it + 1 < nIters);
        if (more) load_tiles((it + 1) * 32);   // LDGs overlap compute below

#pragma unroll
        for (int ks = 0; ks < 2; ks++) {
            const int kr = ks * 8;
            uint32_t a[2][4], b[8][2];
#pragma unroll
            for (int mi = 0; mi < 2; mi++) {
                int m = wm0 + mi * 16;
                a[mi][0] = As[cur][kr + t][m + g];
                a[mi][1] = As[cur][kr + t][m + g + 8];
                a[mi][2] = As[cur][kr + t + 4][m + g];
                a[mi][3] = As[cur][kr + t + 4][m + g + 8];
            }
#pragma unroll
            for (int nj = 0; nj < 8; nj++) {
                int n = wn0 + nj * 8;
                b[nj][0] = Bs[cur][kr + t][n + g];
                b[nj][1] = Bs[cur][kr + t + 4][n + g];
            }
#pragma unroll
            for (int mi = 0; mi < 2; mi++)
#pragma unroll
                for (int nj = 0; nj < 8; nj++)
                    mma_bf16(acc[mi][nj], a[mi], b[nj]);
        }

        if (!more) break;
        store_stage(1 - cur);
        __syncthreads();
    }

    // epilogue: bias (3 modes) + relu, bf16x2 or fp32 stores
    __nv_bfloat16* Cb = (__nv_bfloat16*)Cout;
    float*         Cf = (float*)Cout;
#pragma unroll
    for (int mi = 0; mi < 2; mi++) {
        const int r0 = co0 + wm0 + mi * 16 + g;
        const int r1 = r0 + 8;
        float brs0 = 0.f, brs1 = 0.f;
        if (bias_mode == 0) { brs0 = bias[r0]; brs1 = bias[r1]; }
#pragma unroll
        for (int nj = 0; nj < 8; nj++) {
            const int cb = col0 + wn0 + nj * 8 + 2 * t;
            float b00, b01, b10, b11;
            if (bias_mode == 0) {
                b00 = b01 = brs0; b10 = b11 = brs1;
            } else if (bias_mode == 1) {
                int nid = cb >> 6;
                b00 = b01 = bias[(size_t)r0 * COLSN + nid];
                b10 = b11 = bias[(size_t)r1 * COLSN + nid];
            } else {
                int n0 = cb / 9, n1 = (cb + 1) / 9;
                b00 = bias[(size_t)r0 * COLSN + n0];
                b01 = bias[(size_t)r0 * COLSN + n1];
                b10 = bias[(size_t)r1 * COLSN + n0];
                b11 = bias[(size_t)r1 * COLSN + n1];
            }
            float v0 = acc[mi][nj][0] + b00;
            float v1 = acc[mi][nj][1] + b01;
            float v2 = acc[mi][nj][2] + b10;
            float v3 = acc[mi][nj][3] + b11;
            if (do_relu) {
                v0 = fmaxf(v0, 0.f); v1 = fmaxf(v1, 0.f);
                v2 = fmaxf(v2, 0.f); v3 = fmaxf(v3, 0.f);
            }
            if (store_bf16) {
                *reinterpret_cast<uint32_t*>(&Cb[(size_t)r0 * Ncols + cb]) = pack_bf16(v0, v1);
                *reinterpret_cast<uint32_t*>(&Cb[(size_t)r1 * Ncols + cb]) = pack_bf16(v2, v3);
            } else {
                *reinterpret_cast<float2*>(&Cf[(size_t)r0 * Ncols + cb]) = make_float2(v0, v1);
                *reinterpret_cast<float2*>(&Cf[(size_t)r1 * Ncols + cb]) = make_float2(v2, v3);
            }
        }
    }
}

// ---------------- ball query: first 64 in-ball indices in index order -----
__global__ void ball_query_kernel(const float* __restrict__ x,
                                  const float* __restrict__ node,
                                  int* __restrict__ idxout)
{
    int w = (blockIdx.x * blockDim.x + threadIdx.x) >> 5;
    int lane = threadIdx.x & 31;
    if (w >= BB * MM) return;
    int b = w / MM, m = w % MM;
    float nx = node[(b * 3 + 0) * MM + m];
    float ny = node[(b * 3 + 1) * MM + m];
    float nz = node[(b * 3 + 2) * MM + m];
    const float* xb = x + (size_t)b * 3 * NN;
    int base = w * 64;
    int total = 0;
    int firstJ = -1;
    for (int j0 = 0; j0 < NN; j0 += 32) {
        int j = j0 + lane;
        float dx = xb[j] - nx;
        float dy = xb[NN + j] - ny;
        float dz = xb[2 * NN + j] - nz;
        float d = dx * dx + dy * dy + dz * dz;
        bool hit = d < 4.0f;
        unsigned mask = __ballot_sync(0xffffffffu, hit);
        if (firstJ < 0 && mask) firstJ = j0 + __ffs(mask) - 1;
        int pos = total + __popc(mask & ((1u << lane) - 1u));
        if (hit && pos < 64) idxout[base + pos] = j;
        total += __popc(mask);
        if (total >= 64) break;
    }
    if (total < 64) {
        int f = (firstJ < 0) ? 0 : firstJ;
        for (int p = total + lane; p < 64; p += 32) idxout[base + p] = f;
    }
}

// ---------------- gather ball neighborhood: X0 (6 x COLS1), bf16 ----------
__global__ void gather_xb_kernel(const float* __restrict__ x,
                                 const float* __restrict__ sn,
                                 const float* __restrict__ node,
                                 const int* __restrict__ idx,
                                 __nv_bfloat16* __restrict__ X0)
{
    int col = blockIdx.x * blockDim.x + threadIdx.x;
    if (col >= COLS1) return;
    int nodeid = col >> 6;          // b*MM + m
    int b = nodeid / MM, m = nodeid % MM;
    int j = idx[col];
    const float* xb = x  + (size_t)b * 3 * NN;
    const float* sb = sn + (size_t)b * 3 * NN;
    X0[(size_t)0 * COLS1 + col] = __float2bfloat16(xb[j]          - node[(b * 3 + 0) * MM + m]);
    X0[(size_t)1 * COLS1 + col] = __float2bfloat16(xb[NN + j]     - node[(b * 3 + 1) * MM + m]);
    X0[(size_t)2 * COLS1 + col] = __float2bfloat16(xb[2 * NN + j] - node[(b * 3 + 2) * MM + m]);
    X0[(size_t)3 * COLS1 + col] = __float2bfloat16(sb[j]);
    X0[(size_t)4 * COLS1 + col] = __float2bfloat16(sb[NN + j]);
    X0[(size_t)5 * COLS1 + col] = __float2bfloat16(sb[2 * NN + j]);
}

// -------- per-node max over k=64 (bf16 in/out). grid(COLSN, rows/8), blk(32,8)
__global__ void max64_rows_kernel(const __nv_bfloat16* __restrict__ f,
                                  __nv_bfloat16* __restrict__ Hrows)
{
    int nodeid = blockIdx.x;
    int row = blockIdx.y * 8 + threadIdx.y;
    int lane = threadIdx.x;          // 0..31
    __nv_bfloat162 p = *reinterpret_cast<const __nv_bfloat162*>(
        &f[(size_t)row * COLS1 + nodeid * 64 + lane * 2]);
    float v = fmaxf(__bfloat162float(p.x), __bfloat162float(p.y));
#pragma unroll
    for (int o = 16; o; o >>= 1) v = fmaxf(v, __shfl_xor_sync(0xffffffffu, v, o));
    if (lane == 0) Hrows[(size_t)row * COLSN + nodeid] = __float2bfloat16(v);
}

// -------- per-node max over k=9 (bf16 in/out) -----------------------------
__global__ void max9_rows_kernel(const __nv_bfloat16* __restrict__ g,
                                 __nv_bfloat16* __restrict__ Hrows, int rows)
{
    int e = blockIdx.x * blockDim.x + threadIdx.x;
    if (e >= rows * COLSN) return;
    int row = e / COLSN, nid = e % COLSN;
    size_t base = (size_t)row * COLS2 + nid * 9;
    float mx = -3.4e38f;
#pragma unroll
    for (int k = 0; k < 9; k++) mx = fmaxf(mx, __bfloat162float(g[base + k]));
    Hrows[(size_t)row * COLSN + nid] = __float2bfloat16(mx);
}

// ---------------- 9-NN among nodes (tie-break: smaller index) -------------
__global__ void knn_select_kernel(const float* __restrict__ node,
                                  int* __restrict__ knnidx)
{
    int nid = blockIdx.x;           // 0..2047
    int b = nid >> 9, m = nid & 511;
    int j = threadIdx.x;            // 0..511
    __shared__ float rd[16];
    __shared__ int   ri[16];
    __shared__ int   sbest;
    float nx = node[(b * 3 + 0) * MM + m];
    float ny = node[(b * 3 + 1) * MM + m];
    float nz = node[(b * 3 + 2) * MM + m];
    float dx = node[(b * 3 + 0) * MM + j] - nx;
    float dy = node[(b * 3 + 1) * MM + j] - ny;
    float dz = node[(b * 3 + 2) * MM + j] - nz;
    float d = dx * dx + dy * dy + dz * dz;
    for (int t = 0; t < 9; t++) {
        float bd = d; int bi = j;
#pragma unroll
        for (int o = 16; o; o >>= 1) {
            float od = __shfl_xor_sync(0xffffffffu, bd, o);
            int   oi = __shfl_xor_sync(0xffffffffu, bi, o);
            if (od < bd || (od == bd && oi < bi)) { bd = od; bi = oi; }
        }
        if ((j & 31) == 0) { rd[j >> 5] = bd; ri[j >> 5] = bi; }
        __syncthreads();
        if (j == 0) {
            float best = rd[0]; int besti = ri[0];
            for (int w = 1; w < 16; w++)
                if (rd[w] < best || (rd[w] == best && ri[w] < besti)) { best = rd[w]; besti = ri[w]; }
            knnidx[nid * 9 + t] = besti;
            sbest = besti;
        }
        __syncthreads();
        if (j == sbest) d = 3.4e38f;
    }
}

// -------- gather knn inputs: g0 (131 x COLS2) bf16 ------------------------
__global__ void gather_knn_kernel(const float* __restrict__ node,
                                  const __nv_bfloat16* __restrict__ H,  // feat1
                                  const int* __restrict__ knnidx,
                                  __nv_bfloat16* __restrict__ g0)
{
    int e = blockIdx.x * blockDim.x + threadIdx.x;
    if (e >= 131 * COLS2) return;
    int row = e / COLS2, col = e % COLS2;
    int nid = col / 9;
    int b = nid >> 9, m = nid & 511;
    int j = knnidx[col];
    __nv_bfloat16 v;
    if (row < 3)
        v = __float2bfloat16(node[(b * 3 + row) * MM + j] - node[(b * 3 + row) * MM + m]);
    else
        v = H[(size_t)(row - 3) * COLSN + b * MM + j];
    g0[e] = v;
}

// -------- head: mlp3 (4x256) + softplus + assemble final output ----------
__global__ void head_kernel(const __nv_bfloat16* __restrict__ m2,  // 256 x 2048
                            const float* __restrict__ w3,          // 4 x 256
                            const float* __restrict__ b3,          // 4
                            const float* __restrict__ node,
                            float* __restrict__ out)
{
    int col = blockIdx.x * blockDim.x + threadIdx.x;
    if (col >= COLSN) return;
    int b = col >> 9, m = col & 511;
    float acc0 = b3[0], acc1 = b3[1], acc2 = b3[2], acc3 = b3[3];
    for (int ci = 0; ci < 256; ci++) {
        float xv = __bfloat162float(m2[(size_t)ci * COLSN + col]);
        acc0 += w3[0 * 256 + ci] * xv;
        acc1 += w3[1 * 256 + ci] * xv;
        acc2 += w3[2 * 256 + ci] * xv;
        acc3 += w3[3 * 256 + ci] * xv;
    }
    float kv[3] = {acc0, acc1, acc2};
#pragma unroll
    for (int c = 0; c < 3; c++) {
        float nv = node[(b * 3 + c) * MM + m];
        out[(b * 3 + c) * MM + m] = nv;                   // node passthrough
        out[6144 + (b * 3 + c) * MM + m] = kv[c] + nv;    // keypoints
    }
    float s = acc3;
    float sp = fmaxf(s, 0.f) + log1pf(expf(-fabsf(s)));
    out[12288 + b * MM + m] = sp + 0.001f;
}

// ------------------------------- launcher --------------------------------
extern "C" void kernel_launch(void* const* d_in, const int* in_sizes, int n_in,
                              void* d_out, int out_size)
{
    const float* x    = (const float*)d_in[0];
    const float* sn   = (const float*)d_in[1];
    const float* node = (const float*)d_in[2];
    const float* conv1_w = (const float*)d_in[3];  const float* conv1_b = (const float*)d_in[4];
    const float* conv2_w = (const float*)d_in[5];  const float* conv2_b = (const float*)d_in[6];
    const float* conv3_w = (const float*)d_in[7];  const float* conv3_b = (const float*)d_in[8];
    const float* conv4_w = (const float*)d_in[9];  const float* conv4_b = (const float*)d_in[10];
    const float* conv5_w = (const float*)d_in[11]; const float* conv5_b = (const float*)d_in[12];
    const float* knnb1_w = (const float*)d_in[13]; const float* knnb1_b = (const float*)d_in[14];
    const float* knnb2_w = (const float*)d_in[15]; const float* knnb2_b = (const float*)d_in[16];
    const float* knnb3_w = (const float*)d_in[17]; const float* knnb3_b = (const float*)d_in[18];
    const float* knna1_w = (const float*)d_in[19]; const float* knna1_b = (const float*)d_in[20];
    const float* knna2_w = (const float*)d_in[21]; const float* knna2_b = (const float*)d_in[22];
    const float* mlp1_w  = (const float*)d_in[23]; const float* mlp1_b  = (const float*)d_in[24];
    const float* mlp2_w  = (const float*)d_in[25]; const float* mlp2_b  = (const float*)d_in[26];
    const float* mlp3_w  = (const float*)d_in[27]; const float* mlp3_b  = (const float*)d_in[28];
    float* out = (float*)d_out;

    __nv_bfloat16 *bufA, *bufB, *X0, *H, *tmp1;
    float *tmp2;
    int *ballidx, *knnidx;
    cudaGetSymbolAddress((void**)&bufA, d_bufA);
    cudaGetSymbolAddress((void**)&bufB, d_bufB);
    cudaGetSymbolAddress((void**)&X0,   d_X0);
    cudaGetSymbolAddress((void**)&H,    d_H);
    cudaGetSymbolAddress((void**)&tmp1, d_tmp1);
    cudaGetSymbolAddress((void**)&tmp2, d_tmp2);
    cudaGetSymbolAddress((void**)&ballidx, d_ballidx);
    cudaGetSymbolAddress((void**)&knnidx,  d_knnidx);

    // ---- ball branch ----
    ball_query_kernel<<<(BB * MM * 32 + 255) / 256, 256>>>(x, node, ballidx);
    gather_xb_kernel<<<(COLS1 + 255) / 256, 256>>>(x, sn, node, ballidx, X0);

    // conv1..3: M=64 -> <2,4> (BM=64, BN=256)
    gemm_bf16<2, 4><<<dim3(COLS1 / 256, 1), 256>>>(conv1_w, 6,  X0,   conv1_b, 0, bufA, 1, 6,  COLS1, 1);
    gemm_bf16<2, 4><<<dim3(COLS1 / 256, 1), 256>>>(conv2_w, 64, bufA, conv2_b, 0, bufB, 1, 64, COLS1, 1);
    gemm_bf16<2, 4><<<dim3(COLS1 / 256, 1), 256>>>(conv3_w, 64, bufB, conv3_b, 0, bufA, 1, 64, COLS1, 1);

    // fmax (64 x 2048), then Z4 = conv4_w[:,64:128] @ fmax + b4 (fp32, no relu)
    max64_rows_kernel<<<dim3(COLSN, 8), dim3(32, 8)>>>(bufA, tmp1);
    gemm_bf16<4, 2><<<dim3(COLSN / 128, 1), 256>>>(conv4_w + 64, 128, tmp1, conv4_b, 0, tmp2, 0, 64, COLSN, 0);
    // conv4: relu(conv4_w[:,0:64] @ f3 + Z4[row][col>>6])
    gemm_bf16<4, 2><<<dim3(COLS1 / 128, 1), 256>>>(conv4_w, 128, bufA, tmp2, 1, bufB, 1, 64, COLS1, 1);
    gemm_bf16<4, 2><<<dim3(COLS1 / 128, 1), 256>>>(conv5_w, 128, bufB, conv5_b, 0, bufA, 1, 128, COLS1, 1);
    max64_rows_kernel<<<dim3(COLSN, 16), dim3(32, 8)>>>(bufA, H);   // feat1 -> H rows 0..127

    // ---- knn branch ----
    knn_select_kernel<<<COLSN, 512>>>(node, knnidx);
    gather_knn_kernel<<<(131 * COLS2 + 255) / 256, 256>>>(node, H, knnidx, bufA);
    gemm_bf16<4, 2><<<dim3(COLS2 / 128, 2), 256>>>(knnb1_w, 131, bufA, knnb1_b, 0, bufB, 1, 131, COLS2, 1);
    gemm_bf16<4, 2><<<dim3(COLS2 / 128, 2), 256>>>(knnb2_w, 256, bufB, knnb2_b, 0, bufA, 1, 256, COLS2, 1);
    gemm_bf16<4, 2><<<dim3(COLS2 / 128, 2), 256>>>(knnb3_w, 256, bufA, knnb3_b, 0, bufB, 1, 256, COLS2, 1);

    // gmax (256 x 2048), then Zk = knna1_w[:,256:512] @ gmax + b (fp32, no relu)
    max9_rows_kernel<<<(256 * COLSN + 255) / 256, 256>>>(bufB, tmp1, 256);
    gemm_bf16<4, 2><<<dim3(COLSN / 128, 4), 256>>>(knna1_w + 256, 512, tmp1, knna1_b, 0, tmp2, 0, 256, COLSN, 0);
    // knna1: relu(knna1_w[:,0:256] @ g3 + Zk[row][col/9])
    gemm_bf16<4, 2><<<dim3(COLS2 / 128, 4), 256>>>(knna1_w, 512, bufB, tmp2, 2, bufA, 1, 256, COLS2, 1);
    gemm_bf16<4, 2><<<dim3(COLS2 / 128, 4), 256>>>(knna2_w, 512, bufA, knna2_b, 0, bufB, 1, 512, COLS2, 1);
    max9_rows_kernel<<<(512 * COLSN + 255) / 256, 256>>>(bufB, H + (size_t)128 * COLSN, 512);

    // ---- mlp head ----
    gemm_bf16<4, 2><<<dim3(COLSN / 128, 4), 256>>>(mlp1_w, 640, H,    mlp1_b, 0, bufA, 1, 640, COLSN, 1);
    gemm_bf16<4, 2><<<dim3(COLSN / 128, 2), 256>>>(mlp2_w, 512, bufA, mlp2_b, 0, bufB, 1, 512, COLSN, 1);
    head_kernel<<<(COLSN + 255) / 256, 256>>>(bufB, mlp3_w, mlp3_b, node, out);

    (void)in_sizes; (void)n_in; (void)out_size;
}

// round 14
// speedup vs baseline: 1.2458x; 1.2456x over previous
#include <cuda_runtime.h>
#include <cuda_bf16.h>
#include <math.h>
#include <stdint.h>

#define BB 4
#define NN 16384
#define MM 512
#define COLS1 131072
#define COLS2 18432
#define COLSN 2048

// packed ball-branch weights (u32 = bf16 pair), padded strides
#define OFF1 0        // conv1: 64 x 20
#define OFF2 1280     // conv2: 64 x 36
#define OFF3 3584     // conv3: 64 x 36
#define OFF4 5888     // conv4a: 128 x 36 (cols 0..63)
#define OFF5 10496    // conv5: 128 x 68
#define WTOT 19200

// ---------------- static scratch ----------------
__device__ __nv_bfloat16 d_bufA[128 * 131072];
__device__ __nv_bfloat16 d_bufB[128 * 131072];
__device__ uint32_t      d_X0p[3 * COLS1];       // packed ball input pairs
__device__ uint32_t      d_Wp[WTOT];
__device__ __nv_bfloat16 d_H[640 * 2048];
__device__ __nv_bfloat16 d_tmp1[512 * 2048];
__device__ float         d_tmp2[512 * 2048];
__device__ int   d_ballidx[131072];
__device__ int   d_knnidx[18432];

__device__ __forceinline__ uint32_t pack_bf16(float lo, float hi) {
    __nv_bfloat162 h = __floats2bfloat162_rn(lo, hi);
    return *reinterpret_cast<uint32_t*>(&h);
}
__device__ __forceinline__ void mma_bf16(float c[4], const uint32_t a[4], const uint32_t b[2]) {
    asm volatile(
        "mma.sync.aligned.m16n8k16.row.col.f32.bf16.bf16.f32 "
        "{%0,%1,%2,%3}, {%4,%5,%6,%7}, {%8,%9}, {%0,%1,%2,%3};"
        : "+f"(c[0]), "+f"(c[1]), "+f"(c[2]), "+f"(c[3])
        : "r"(a[0]), "r"(a[1]), "r"(a[2]), "r"(a[3]), "r"(b[0]), "r"(b[1]));
}

// -------- weight preconvert: fp32 [M][lda] -> packed pairs [M][S] (zero-pad)
__global__ void convW(const float* __restrict__ src, int lda, int M, int K,
                      int S, uint32_t* __restrict__ dst)
{
    int i = blockIdx.x * blockDim.x + threadIdx.x;
    if (i >= M * S) return;
    int m = i / S, p = i % S;
    float v0 = (2 * p     < K) ? src[(size_t)m * lda + 2 * p]     : 0.f;
    float v1 = (2 * p + 1 < K) ? src[(size_t)m * lda + 2 * p + 1] : 0.f;
    dst[i] = pack_bf16(v0, v1);
}

// -------- one fused-layer pass over smem-resident B and weights ----------
// EPI: 0 = packed act out; 1 = act out + per-node fmax; 2 = act out, bias=ZS;
//      3 = per-node max -> H
template<int WROWS, int EPI>
__device__ __forceinline__ void pass(const uint32_t* __restrict__ Wsm, int S, int ktiles,
    const uint32_t (*__restrict__ B)[264], int colbase,
    const float* __restrict__ bias, const float* __restrict__ ZS,
    uint32_t (*__restrict__ O)[264], float* __restrict__ fmaxS,
    __nv_bfloat16* __restrict__ Hout, int node0)
{
    constexpr int WCC = 8 / WROWS;
    const int tid = threadIdx.x, lane = tid & 31, wid = tid >> 5;
    const int g = lane >> 2, t = lane & 3;
    const int wr = wid / WCC, wc = wid % WCC;
    const int wm0 = wr * 32, wn0 = colbase + wc * 64;

    float acc[2][8][4];
#pragma unroll
    for (int mi = 0; mi < 2; mi++)
#pragma unroll
        for (int nj = 0; nj < 8; nj++)
#pragma unroll
            for (int q = 0; q < 4; q++) acc[mi][nj][q] = 0.f;

    for (int kt = 0; kt < ktiles; kt++) {
#pragma unroll
        for (int ks = 0; ks < 2; ks++) {
            const int kp = kt * 16 + ks * 8;
            uint32_t a[2][4];
#pragma unroll
            for (int mi = 0; mi < 2; mi++) {
                const uint32_t* w0 = Wsm + (wm0 + mi * 16 + g) * S + kp;
                a[mi][0] = w0[t];         a[mi][2] = w0[t + 4];
                a[mi][1] = w0[8 * S + t]; a[mi][3] = w0[8 * S + t + 4];
            }
            uint32_t b[8][2];
#pragma unroll
            for (int nj = 0; nj < 8; nj++) {
                int n = wn0 + nj * 8 + g;
                b[nj][0] = B[kp + t][n];
                b[nj][1] = B[kp + t + 4][n];
            }
#pragma unroll
            for (int mi = 0; mi < 2; mi++)
#pragma unroll
                for (int nj = 0; nj < 8; nj++)
                    mma_bf16(acc[mi][nj], a[mi], b[nj]);
        }
    }

#pragma unroll
    for (int mi = 0; mi < 2; mi++) {
        const int r = wm0 + mi * 16 + g;
        float b0, b1;
        if (EPI == 2) { int nd = wn0 >> 6; b0 = ZS[r * 4 + nd]; b1 = ZS[(r + 8) * 4 + nd]; }
        else          { b0 = bias[r]; b1 = bias[r + 8]; }
        float mx0 = -3.4e38f, mx1 = -3.4e38f;
#pragma unroll
        for (int nj = 0; nj < 8; nj++) {
            float o0 = fmaxf(acc[mi][nj][0] + b0, 0.f);
            float o1 = fmaxf(acc[mi][nj][1] + b0, 0.f);
            float o2 = fmaxf(acc[mi][nj][2] + b1, 0.f);
            float o3 = fmaxf(acc[mi][nj][3] + b1, 0.f);
            if (EPI == 3) {
                mx0 = fmaxf(mx0, fmaxf(o0, o1));
                mx1 = fmaxf(mx1, fmaxf(o2, o3));
            } else {
                if (EPI == 1) { mx0 = fmaxf(mx0, fmaxf(o0, o1)); mx1 = fmaxf(mx1, fmaxf(o2, o3)); }
                float p0 = __shfl_xor_sync(0xffffffffu, o0, 4);
                float p1 = __shfl_xor_sync(0xffffffffu, o1, 4);
                float p2 = __shfl_xor_sync(0xffffffffu, o2, 4);
                float p3 = __shfl_xor_sync(0xffffffffu, o3, 4);
                if (!(g & 1)) {
                    int pr = r >> 1, c = wn0 + nj * 8 + 2 * t;
                    O[pr][c]         = pack_bf16(o0, p0);
                    O[pr][c + 1]     = pack_bf16(o1, p1);
                    O[pr + 4][c]     = pack_bf16(o2, p2);
                    O[pr + 4][c + 1] = pack_bf16(o3, p3);
                }
            }
        }
        if (EPI == 1 || EPI == 3) {
            mx0 = fmaxf(mx0, __shfl_xor_sync(0xffffffffu, mx0, 1));
            mx0 = fmaxf(mx0, __shfl_xor_sync(0xffffffffu, mx0, 2));
            mx1 = fmaxf(mx1, __shfl_xor_sync(0xffffffffu, mx1, 1));
            mx1 = fmaxf(mx1, __shfl_xor_sync(0xffffffffu, mx1, 2));
            if (t == 0) {
                int nd = wn0 >> 6;
                if (EPI == 1) { fmaxS[r * 4 + nd] = mx0; fmaxS[(r + 8) * 4 + nd] = mx1; }
                else {
                    Hout[(size_t)r * COLSN + node0 + nd]       = __float2bfloat16(mx0);
                    Hout[(size_t)(r + 8) * COLSN + node0 + nd] = __float2bfloat16(mx1);
                }
            }
        }
    }
}

// -------- fused ball branch: conv1..conv5 + fmax + Z4 + node-max -> H -----
__global__ void __launch_bounds__(256, 1)
fused_ball(const uint32_t* __restrict__ Wp, const uint32_t* __restrict__ X0p,
           const float* __restrict__ b1, const float* __restrict__ b2,
           const float* __restrict__ b3,
           const float* __restrict__ c4w, const float* __restrict__ c4b,
           const float* __restrict__ b5, __nv_bfloat16* __restrict__ H)
{
    extern __shared__ uint32_t sm[];
    uint32_t (*P)[264] = (uint32_t(*)[264])sm;            // 64 pair-rows
    uint32_t (*Q)[264] = (uint32_t(*)[264])(sm + 16896);  // 32 pair-rows
    uint32_t* Wall = sm + 25344;                          // 19200
    float* fmaxS = (float*)(sm + 44544);                  // 64 x 4
    float* ZS    = (float*)(sm + 44800);                  // 128 x 4
    const int tid = threadIdx.x;
    const int col0 = blockIdx.x * 256;

    for (int i = tid; i < WTOT; i += 256) Wall[i] = Wp[i];
    for (int i = tid; i < 768; i += 256)
        P[i >> 8][i & 255] = X0p[(size_t)(i >> 8) * COLS1 + col0 + (i & 255)];
    for (int i = tid; i < 13 * 264; i += 256) P[3 + i / 264][i % 264] = 0;
    __syncthreads();

    pass<2, 0>(Wall + OFF1, 20, 1, P, 0, b1, nullptr, Q, nullptr, nullptr, 0);
    __syncthreads();
    pass<2, 0>(Wall + OFF2, 36, 2, Q, 0, b2, nullptr, P, nullptr, nullptr, 0);
    __syncthreads();
    pass<2, 1>(Wall + OFF3, 36, 2, P, 0, b3, nullptr, Q, fmaxS, nullptr, 0);
    __syncthreads();
    // Z4[row][node] = conv4_w[:,64:128] @ fmax + b4 (fp32)
    for (int i = tid; i < 512; i += 256) {
        int row = i >> 2, nd = i & 3;
        float d = c4b[row];
        const float* wr = c4w + row * 128 + 64;
#pragma unroll 8
        for (int k = 0; k < 64; k++) d += wr[k] * fmaxS[k * 4 + nd];
        ZS[i] = d;
    }
    __syncthreads();
    pass<4, 2>(Wall + OFF4, 36, 2, Q, 0, nullptr, ZS, P, nullptr, nullptr, 0);
    __syncthreads();
    pass<4, 3>(Wall + OFF5, 68, 4, P, 0, b5, nullptr, nullptr, nullptr, H, col0 >> 6);
    pass<4, 2>(Wall + OFF4, 36, 2, Q, 128, nullptr, ZS, P, nullptr, nullptr, 0);
    __syncthreads();
    pass<4, 3>(Wall + OFF5, 68, 4, P, 128, b5, nullptr, nullptr, nullptr, H, col0 >> 6);
}

// ---------------- generic bf16 GEMM (knn/mlp path, unchanged) -------------
template<int WR, int WC>
__global__ void __launch_bounds__(WR*WC*32, 2)
gemm_bf16(const float* __restrict__ W, int lda,
          const __nv_bfloat16* __restrict__ X,
          const float* __restrict__ bias, int bias_mode,
          void* __restrict__ Cout, int store_bf16,
          int K, int Ncols, int do_relu)
{
    constexpr int BM = WR * 32;
    constexpr int BN = WC * 64;
    constexpr int NT = WR * WC * 32;
    constexpr int KP = 16;
    constexpr int SA = BM + 8;
    constexpr int SB = BN + 8;
    constexpr int AS = NT / BM;
    constexpr int AI = KP / AS;
    constexpr int N8 = BN / 8;
    constexpr int BS = NT / N8;
    constexpr int BI = KP / BS;

    __shared__ __align__(16) uint32_t As[2][KP][SA];
    __shared__ __align__(16) uint32_t Bs[2][KP][SB];

    const int tid  = threadIdx.x;
    const int lane = tid & 31;
    const int wid  = tid >> 5;
    const int g = lane >> 2;
    const int t = lane & 3;
    const int wm0 = (wid / WC) * 32;
    const int wn0 = (wid % WC) * 64;
    const int co0  = blockIdx.y * BM;
    const int col0 = blockIdx.x * BN;

    const int a_row = tid % BM;
    const int a_k0  = tid / BM;
    const int b_n8  = tid % N8;
    const int b_k0  = tid / N8;

    float acc[2][8][4];
#pragma unroll
    for (int mi = 0; mi < 2; mi++)
#pragma unroll
        for (int nj = 0; nj < 8; nj++)
#pragma unroll
            for (int q = 0; q < 4; q++) acc[mi][nj][q] = 0.f;

    uint32_t aReg[AI];
    uint4    bReg[BI][2];
    const float* wp = W + (size_t)(co0 + a_row) * lda;

    auto load_tiles = [&](int k0) {
#pragma unroll
        for (int i = 0; i < AI; i++) {
            int kg = k0 + 2 * (a_k0 + i * AS);
            float v0 = (kg     < K) ? __ldg(wp + kg)     : 0.f;
            float v1 = (kg + 1 < K) ? __ldg(wp + kg + 1) : 0.f;
            aReg[i] = pack_bf16(v0, v1);
        }
#pragma unroll
        for (int i = 0; i < BI; i++) {
            int kg = k0 + 2 * (b_k0 + i * BS);
            uint4 u0 = make_uint4(0, 0, 0, 0), u1 = u0;
            if (kg < K)
                u0 = *reinterpret_cast<const uint4*>(&X[(size_t)kg * Ncols + col0 + b_n8 * 8]);
            if (kg + 1 < K)
                u1 = *reinterpret_cast<const uint4*>(&X[(size_t)(kg + 1) * Ncols + col0 + b_n8 * 8]);
            bReg[i][0] = make_uint4(__byte_perm(u0.x, u1.x, 0x5410), __byte_perm(u0.x, u1.x, 0x7632),
                                    __byte_perm(u0.y, u1.y, 0x5410), __byte_perm(u0.y, u1.y, 0x7632));
            bReg[i][1] = make_uint4(__byte_perm(u0.z, u1.z, 0x5410), __byte_perm(u0.z, u1.z, 0x7632),
                                    __byte_perm(u0.w, u1.w, 0x5410), __byte_perm(u0.w, u1.w, 0x7632));
        }
    };
    auto store_stage = [&](int s) {
#pragma unroll
        for (int i = 0; i < AI; i++)
            As[s][a_k0 + i * AS][a_row] = aReg[i];
#pragma unroll
        for (int i = 0; i < BI; i++) {
            *reinterpret_cast<uint4*>(&Bs[s][b_k0 + i * BS][b_n8 * 8])     = bReg[i][0];
            *reinterpret_cast<uint4*>(&Bs[s][b_k0 + i * BS][b_n8 * 8 + 4]) = bReg[i][1];
        }
    };

    const int nIters = (K + 31) / 32;
    load_tiles(0);
    store_stage(0);
    __syncthreads();

    for (int it = 0; ; it++) {
        const int cur = it & 1;
        const bool more = (it + 1 < nIters);
        if (more) load_tiles((it + 1) * 32);

#pragma unroll
        for (int ks = 0; ks < 2; ks++) {
            const int kr = ks * 8;
            uint32_t a[2][4], b[8][2];
#pragma unroll
            for (int mi = 0; mi < 2; mi++) {
                int m = wm0 + mi * 16;
                a[mi][0] = As[cur][kr + t][m + g];
                a[mi][1] = As[cur][kr + t][m + g + 8];
                a[mi][2] = As[cur][kr + t + 4][m + g];
                a[mi][3] = As[cur][kr + t + 4][m + g + 8];
            }
#pragma unroll
            for (int nj = 0; nj < 8; nj++) {
                int n = wn0 + nj * 8;
                b[nj][0] = Bs[cur][kr + t][n + g];
                b[nj][1] = Bs[cur][kr + t + 4][n + g];
            }
#pragma unroll
            for (int mi = 0; mi < 2; mi++)
#pragma unroll
                for (int nj = 0; nj < 8; nj++)
                    mma_bf16(acc[mi][nj], a[mi], b[nj]);
        }

        if (!more) break;
        store_stage(1 - cur);
        __syncthreads();
    }

    __nv_bfloat16* Cb = (__nv_bfloat16*)Cout;
    float*         Cf = (float*)Cout;
#pragma unroll
    for (int mi = 0; mi < 2; mi++) {
        const int r0 = co0 + wm0 + mi * 16 + g;
        const int r1 = r0 + 8;
        float brs0 = 0.f, brs1 = 0.f;
        if (bias_mode == 0) { brs0 = bias[r0]; brs1 = bias[r1]; }
#pragma unroll
        for (int nj = 0; nj < 8; nj++) {
            const int cb = col0 + wn0 + nj * 8 + 2 * t;
            float b00, b01, b10, b11;
            if (bias_mode == 0) {
                b00 = b01 = brs0; b10 = b11 = brs1;
            } else {
                int n0 = cb / 9, n1 = (cb + 1) / 9;
                b00 = bias[(size_t)r0 * COLSN + n0];
                b01 = bias[(size_t)r0 * COLSN + n1];
                b10 = bias[(size_t)r1 * COLSN + n0];
                b11 = bias[(size_t)r1 * COLSN + n1];
            }
            float v0 = acc[mi][nj][0] + b00;
            float v1 = acc[mi][nj][1] + b01;
            float v2 = acc[mi][nj][2] + b10;
            float v3 = acc[mi][nj][3] + b11;
            if (do_relu) {
                v0 = fmaxf(v0, 0.f); v1 = fmaxf(v1, 0.f);
                v2 = fmaxf(v2, 0.f); v3 = fmaxf(v3, 0.f);
            }
            if (store_bf16) {
                *reinterpret_cast<uint32_t*>(&Cb[(size_t)r0 * Ncols + cb]) = pack_bf16(v0, v1);
                *reinterpret_cast<uint32_t*>(&Cb[(size_t)r1 * Ncols + cb]) = pack_bf16(v2, v3);
            } else {
                *reinterpret_cast<float2*>(&Cf[(size_t)r0 * Ncols + cb]) = make_float2(v0, v1);
                *reinterpret_cast<float2*>(&Cf[(size_t)r1 * Ncols + cb]) = make_float2(v2, v3);
            }
        }
    }
}

// ---------------- ball query ----------------------------------------------
__global__ void ball_query_kernel(const float* __restrict__ x,
                                  const float* __restrict__ node,
                                  int* __restrict__ idxout)
{
    int w = (blockIdx.x * blockDim.x + threadIdx.x) >> 5;
    int lane = threadIdx.x & 31;
    if (w >= BB * MM) return;
    int b = w / MM, m = w % MM;
    float nx = node[(b * 3 + 0) * MM + m];
    float ny = node[(b * 3 + 1) * MM + m];
    float nz = node[(b * 3 + 2) * MM + m];
    const float* xb = x + (size_t)b * 3 * NN;
    int base = w * 64;
    int total = 0;
    int firstJ = -1;
    for (int j0 = 0; j0 < NN; j0 += 32) {
        int j = j0 + lane;
        float dx = xb[j] - nx;
        float dy = xb[NN + j] - ny;
        float dz = xb[2 * NN + j] - nz;
        float d = dx * dx + dy * dy + dz * dz;
        bool hit = d < 4.0f;
        unsigned mask = __ballot_sync(0xffffffffu, hit);
        if (firstJ < 0 && mask) firstJ = j0 + __ffs(mask) - 1;
        int pos = total + __popc(mask & ((1u << lane) - 1u));
        if (hit && pos < 64) idxout[base + pos] = j;
        total += __popc(mask);
        if (total >= 64) break;
    }
    if (total < 64) {
        int f = (firstJ < 0) ? 0 : firstJ;
        for (int p = total + lane; p < 64; p += 32) idxout[base + p] = f;
    }
}

// ---------------- gather ball input -> packed pairs -----------------------
__global__ void gather_xb_kernel(const float* __restrict__ x,
                                 const float* __restrict__ sn,
                                 const float* __restrict__ node,
                                 const int* __restrict__ idx,
                                 uint32_t* __restrict__ X0p)
{
    int col = blockIdx.x * blockDim.x + threadIdx.x;
    if (col >= COLS1) return;
    int nodeid = col >> 6;
    int b = nodeid / MM, m = nodeid % MM;
    int j = idx[col];
    const float* xb = x  + (size_t)b * 3 * NN;
    const float* sb = sn + (size_t)b * 3 * NN;
    float d0 = xb[j]          - node[(b * 3 + 0) * MM + m];
    float d1 = xb[NN + j]     - node[(b * 3 + 1) * MM + m];
    float d2 = xb[2 * NN + j] - node[(b * 3 + 2) * MM + m];
    float s0 = sb[j], s1 = sb[NN + j], s2 = sb[2 * NN + j];
    X0p[(size_t)0 * COLS1 + col] = pack_bf16(d0, d1);
    X0p[(size_t)1 * COLS1 + col] = pack_bf16(d2, s0);
    X0p[(size_t)2 * COLS1 + col] = pack_bf16(s1, s2);
}

// -------- per-node max over k=9 (bf16 in/out) ------------------------------
__global__ void max9_rows_kernel(const __nv_bfloat16* __restrict__ g,
                                 __nv_bfloat16* __restrict__ Hrows, int rows)
{
    int e = blockIdx.x * blockDim.x + threadIdx.x;
    if (e >= rows * COLSN) return;
    int row = e / COLSN, nid = e % COLSN;
    size_t base = (size_t)row * COLS2 + nid * 9;
    float mx = -3.4e38f;
#pragma unroll
    for (int k = 0; k < 9; k++) mx = fmaxf(mx, __bfloat162float(g[base + k]));
    Hrows[(size_t)row * COLSN + nid] = __float2bfloat16(mx);
}

// ---------------- 9-NN among nodes ----------------------------------------
__global__ void knn_select_kernel(const float* __restrict__ node,
                                  int* __restrict__ knnidx)
{
    int nid = blockIdx.x;
    int b = nid >> 9, m = nid & 511;
    int j = threadIdx.x;
    __shared__ float rd[16];
    __shared__ int   ri[16];
    __shared__ int   sbest;
    float nx = node[(b * 3 + 0) * MM + m];
    float ny = node[(b * 3 + 1) * MM + m];
    float nz = node[(b * 3 + 2) * MM + m];
    float dx = node[(b * 3 + 0) * MM + j] - nx;
    float dy = node[(b * 3 + 1) * MM + j] - ny;
    float dz = node[(b * 3 + 2) * MM + j] - nz;
    float d = dx * dx + dy * dy + dz * dz;
    for (int t = 0; t < 9; t++) {
        float bd = d; int bi = j;
#pragma unroll
        for (int o = 16; o; o >>= 1) {
            float od = __shfl_xor_sync(0xffffffffu, bd, o);
            int   oi = __shfl_xor_sync(0xffffffffu, bi, o);
            if (od < bd || (od == bd && oi < bi)) { bd = od; bi = oi; }
        }
        if ((j & 31) == 0) { rd[j >> 5] = bd; ri[j >> 5] = bi; }
        __syncthreads();
        if (j == 0) {
            float best = rd[0]; int besti = ri[0];
            for (int w = 1; w < 16; w++)
                if (rd[w] < best || (rd[w] == best && ri[w] < besti)) { best = rd[w]; besti = ri[w]; }
            knnidx[nid * 9 + t] = besti;
            sbest = besti;
        }
        __syncthreads();
        if (j == sbest) d = 3.4e38f;
    }
}

// -------- gather knn inputs -----------------------------------------------
__global__ void gather_knn_kernel(const float* __restrict__ node,
                                  const __nv_bfloat16* __restrict__ H,
                                  const int* __restrict__ knnidx,
                                  __nv_bfloat16* __restrict__ g0)
{
    int e = blockIdx.x * blockDim.x + threadIdx.x;
    if (e >= 131 * COLS2) return;
    int row = e / COLS2, col = e % COLS2;
    int nid = col / 9;
    int b = nid >> 9, m = nid & 511;
    int j = knnidx[col];
    __nv_bfloat16 v;
    if (row < 3)
        v = __float2bfloat16(node[(b * 3 + row) * MM + j] - node[(b * 3 + row) * MM + m]);
    else
        v = H[(size_t)(row - 3) * COLSN + b * MM + j];
    g0[e] = v;
}

// -------- head --------------------------------------------------------------
__global__ void head_kernel(const __nv_bfloat16* __restrict__ m2,
                            const float* __restrict__ w3,
                            const float* __restrict__ b3,
                            const float* __restrict__ node,
                            float* __restrict__ out)
{
    int col = blockIdx.x * blockDim.x + threadIdx.x;
    if (col >= COLSN) return;
    int b = col >> 9, m = col & 511;
    float acc0 = b3[0], acc1 = b3[1], acc2 = b3[2], acc3 = b3[3];
    for (int ci = 0; ci < 256; ci++) {
        float xv = __bfloat162float(m2[(size_t)ci * COLSN + col]);
        acc0 += w3[0 * 256 + ci] * xv;
        acc1 += w3[1 * 256 + ci] * xv;
        acc2 += w3[2 * 256 + ci] * xv;
        acc3 += w3[3 * 256 + ci] * xv;
    }
    float kv[3] = {acc0, acc1, acc2};
#pragma unroll
    for (int c = 0; c < 3; c++) {
        float nv = node[(b * 3 + c) * MM + m];
        out[(b * 3 + c) * MM + m] = nv;
        out[6144 + (b * 3 + c) * MM + m] = kv[c] + nv;
    }
    float s = acc3;
    float sp = fmaxf(s, 0.f) + log1pf(expf(-fabsf(s)));
    out[12288 + b * MM + m] = sp + 0.001f;
}

// ------------------------------- launcher --------------------------------
extern "C" void kernel_launch(void* const* d_in, const int* in_sizes, int n_in,
                              void* d_out, int out_size)
{
    const float* x    = (const float*)d_in[0];
    const float* sn   = (const float*)d_in[1];
    const float* node = (const float*)d_in[2];
    const float* conv1_w = (const float*)d_in[3];  const float* conv1_b = (const float*)d_in[4];
    const float* conv2_w = (const float*)d_in[5];  const float* conv2_b = (const float*)d_in[6];
    const float* conv3_w = (const float*)d_in[7];  const float* conv3_b = (const float*)d_in[8];
    const float* conv4_w = (const float*)d_in[9];  const float* conv4_b = (const float*)d_in[10];
    const float* conv5_w = (const float*)d_in[11]; const float* conv5_b = (const float*)d_in[12];
    const float* knnb1_w = (const float*)d_in[13]; const float* knnb1_b = (const float*)d_in[14];
    const float* knnb2_w = (const float*)d_in[15]; const float* knnb2_b = (const float*)d_in[16];
    const float* knnb3_w = (const float*)d_in[17]; const float* knnb3_b = (const float*)d_in[18];
    const float* knna1_w = (const float*)d_in[19]; const float* knna1_b = (const float*)d_in[20];
    const float* knna2_w = (const float*)d_in[21]; const float* knna2_b = (const float*)d_in[22];
    const float* mlp1_w  = (const float*)d_in[23]; const float* mlp1_b  = (const float*)d_in[24];
    const float* mlp2_w  = (const float*)d_in[25]; const float* mlp2_b  = (const float*)d_in[26];
    const float* mlp3_w  = (const float*)d_in[27]; const float* mlp3_b  = (const float*)d_in[28];
    float* out = (float*)d_out;

    __nv_bfloat16 *bufA, *bufB, *H, *tmp1;
    uint32_t *X0p, *Wp;
    float *tmp2;
    int *ballidx, *knnidx;
    cudaGetSymbolAddress((void**)&bufA, d_bufA);
    cudaGetSymbolAddress((void**)&bufB, d_bufB);
    cudaGetSymbolAddress((void**)&X0p,  d_X0p);
    cudaGetSymbolAddress((void**)&Wp,   d_Wp);
    cudaGetSymbolAddress((void**)&H,    d_H);
    cudaGetSymbolAddress((void**)&tmp1, d_tmp1);
    cudaGetSymbolAddress((void**)&tmp2, d_tmp2);
    cudaGetSymbolAddress((void**)&ballidx, d_ballidx);
    cudaGetSymbolAddress((void**)&knnidx,  d_knnidx);

    // ---- ball branch: query + gather + fused conv1..5 -> H rows 0..127 ----
    ball_query_kernel<<<(BB * MM * 32 + 255) / 256, 256>>>(x, node, ballidx);
    gather_xb_kernel<<<(COLS1 + 255) / 256, 256>>>(x, sn, node, ballidx, X0p);

    convW<<<(64 * 20 + 255) / 256, 256>>>(conv1_w, 6,   64, 6,   20, Wp + OFF1);
    convW<<<(64 * 36 + 255) / 256, 256>>>(conv2_w, 64,  64, 64,  36, Wp + OFF2);
    convW<<<(64 * 36 + 255) / 256, 256>>>(conv3_w, 64,  64, 64,  36, Wp + OFF3);
    convW<<<(128 * 36 + 255) / 256, 256>>>(conv4_w, 128, 128, 64,  36, Wp + OFF4);
    convW<<<(128 * 68 + 255) / 256, 256>>>(conv5_w, 128, 128, 128, 68, Wp + OFF5);

    static int smset = 0;
    if (!smset) {
        cudaFuncSetAttribute(fused_ball, cudaFuncAttributeMaxDynamicSharedMemorySize, 181248);
        smset = 1;
    }
    fused_ball<<<COLS1 / 256, 256, 181248>>>(Wp, X0p, conv1_b, conv2_b, conv3_b,
                                             conv4_w, conv4_b, conv5_b, H);

    // ---- knn branch ----
    knn_select_kernel<<<COLSN, 512>>>(node, knnidx);
    gather_knn_kernel<<<(131 * COLS2 + 255) / 256, 256>>>(node, H, knnidx, bufA);
    gemm_bf16<4, 2><<<dim3(COLS2 / 128, 2), 256>>>(knnb1_w, 131, bufA, knnb1_b, 0, bufB, 1, 131, COLS2, 1);
    gemm_bf16<4, 2><<<dim3(COLS2 / 128, 2), 256>>>(knnb2_w, 256, bufB, knnb2_b, 0, bufA, 1, 256, COLS2, 1);
    gemm_bf16<4, 2><<<dim3(COLS2 / 128, 2), 256>>>(knnb3_w, 256, bufA, knnb3_b, 0, bufB, 1, 256, COLS2, 1);

    max9_rows_kernel<<<(256 * COLSN + 255) / 256, 256>>>(bufB, tmp1, 256);
    gemm_bf16<4, 2><<<dim3(COLSN / 128, 4), 256>>>(knna1_w + 256, 512, tmp1, knna1_b, 0, tmp2, 0, 256, COLSN, 0);
    gemm_bf16<4, 2><<<dim3(COLS2 / 128, 4), 256>>>(knna1_w, 512, bufB, tmp2, 2, bufA, 1, 256, COLS2, 1);
    gemm_bf16<4, 2><<<dim3(COLS2 / 128, 4), 256>>>(knna2_w, 512, bufA, knna2_b, 0, bufB, 1, 512, COLS2, 1);
    max9_rows_kernel<<<(512 * COLSN + 255) / 256, 256>>>(bufB, H + (size_t)128 * COLSN, 512);

    // ---- mlp head ----
    gemm_bf16<4, 2><<<dim3(COLSN / 128, 4), 256>>>(mlp1_w, 640, H,    mlp1_b, 0, bufA, 1, 640, COLSN, 1);
    gemm_bf16<4, 2><<<dim3(COLSN / 128, 2), 256>>>(mlp2_w, 512, bufA, mlp2_b, 0, bufB, 1, 512, COLSN, 1);
    head_kernel<<<(COLSN + 255) / 256, 256>>>(bufB, mlp3_w, mlp3_b, node, out);

    (void)in_sizes; (void)n_in; (void)out_size;
}